// round 5
// baseline (speedup 1.0000x reference)
#include <cuda_runtime.h>
#include <math.h>

#define BB 4
#define CF 16
#define CLIPS 7
#define DC 256
#define KC 8192

typedef unsigned long long u64;

__device__ __forceinline__ u64 pk2(float lo, float hi) {
    u64 r; asm("mov.b64 %0,{%1,%2};" : "=l"(r) : "f"(lo), "f"(hi)); return r;
}
__device__ __forceinline__ void upk2(u64 v, float& lo, float& hi) {
    asm("mov.b64 {%0,%1},%2;" : "=f"(lo), "=f"(hi) : "l"(v));
}
__device__ __forceinline__ u64 fma2(u64 a, u64 b, u64 c) {
    u64 r; asm("fma.rn.f32x2 %0,%1,%2,%3;" : "=l"(r) : "l"(a), "l"(b), "l"(c)); return r;
}

// ---------------- scratch ----------------
__device__ float g_y1[CLIPS*BB*32*CF*96*96];
__device__ float g_p1[CLIPS*BB*32*CF*48*48];
__device__ float g_y2[CLIPS*BB*64*CF*48*48];
__device__ float g_p2[CLIPS*BB*64*CF*24*24];
__device__ float g_y3[CLIPS*BB*128*CF*24*24];
__device__ float g_h [CLIPS*BB*32768];
__device__ float g_feat[BB*CLIPS*DC];
__device__ float g_quant[BB*CLIPS*DC];
__device__ int   g_tok[BB*CLIPS];
__device__ double g_stats[3*CLIPS*256];   // zero-init; finalize re-zeros (replay-safe)
__device__ float g_scale[CLIPS*128];
__device__ float g_shift[CLIPS*128];
__device__ float g_part_s[28*32];
__device__ int   g_part_i[28*32];
__device__ float g_gx[BB*6*768];
__device__ float g_ctx[BB*6*DC];
__device__ float g_scal[2];

// ============ conv3d k=3 pad=1, double-buffered, fused BN stats, v3 ============
// block: (WS/6, TH); grid: (HS/TH, COUT/COT, CLIPS*BB*CF)
template<int CIN, int COUT, int HS, int WS, int TH, int COT, int NT>
__global__ void __launch_bounds__(NT, 5)
conv3d_k(const float* __restrict__ xin, long sclip, long sn, long sc, long sd,
         int doff, const float* __restrict__ w, const float* __restrict__ bias,
         float* __restrict__ y, int stage)
{
    constexpr int PW = 6, PH = 3;
    constexpr int TX = WS/PW;
    constexpr int WPP = WS + 2;                 // even
    constexpr int ROWS = TH + 2;
    constexpr int TOT = ROWS*WPP;
    constexpr int PASSES = (TOT + NT - 1)/NT;
    constexpr int NW = NT/32;

    __shared__ __align__(16) float s_x[2][TOT];
    __shared__ __align__(16) u64  s_w[2][COT*3*4];   // [co][kh][4] (kw 0..2 + pad)
    __shared__ float s_red[NW][COT][2];

    const int tx = threadIdx.x, ty = threadIdx.y;
    const int tid = ty*TX + tx;
    const int lane = tid & 31, wid = tid >> 5;
    const int nd = blockIdx.z;
    const int clip = nd >> 6;
    const int n = (nd >> 4) & 3, d = nd & 15;
    const int h0 = blockIdx.x * TH;
    const int co0 = blockIdx.y * COT;

    const int kd0 = (d == 0) ? 1 : 0;
    const int kdn = 3 - kd0 - ((d == CF-1) ? 1 : 0);
    const int P = CIN * kdn;

    // ---- plane-invariant loader geometry (computed once) ----
    int soff[PASSES], goff[PASSES];
    #pragma unroll
    for (int k=0; k<PASSES; k++) {
        int idx = k*NT + tid;
        if (idx < TOT) {
            int r = idx / WPP, c = idx - r*WPP;
            int hh = h0 + r - 1, ww = c - 1;
            soff[k] = idx;
            goff[k] = (hh >= 0 && hh < HS && (unsigned)ww < (unsigned)WS) ? (hh*WS + ww) : -1;
        } else { soff[k] = -1; goff[k] = -1; }
    }
    const bool wldr = (tid < COT*9);
    int wslot = 0;
    {
        int wco = tid/9, wrem = tid - wco*9;
        int wkh = wrem/3, wkw = wrem - wkh*3;
        wslot = (wco*3 + wkh)*4 + wkw;
    }

    // ---- prefetch stream state (incremental; no division in loop) ----
    const float* pxp = xin + (long)clip*sclip + (long)n*sn
                           + (long)(clip*doff + d + kd0 - 1)*sd;
    const float* pwp;
    {
        int wco = tid/9, wrem = tid - wco*9;
        pwp = w + ((long)(co0+wco)*CIN)*27 + kd0*9 + wrem;
    }
    int pkd = kd0;
    const long xkd_wrap = sc - (long)kdn*sd;
    const int  wkd_wrap = 27 - kdn*9;
    const int  kd_end = kd0 + kdn;

    u64 acc2[COT][PH];
    #pragma unroll
    for (int co=0; co<COT; co++)
        #pragma unroll
        for (int j=0; j<PH; j++) acc2[co][j] = 0ULL;

    float rv[PASSES];
    float wv = 0.f;

    // first prefetch
    #pragma unroll
    for (int k=0; k<PASSES; k++)
        rv[k] = (goff[k] >= 0) ? __ldg(pxp + goff[k]) : 0.f;
    if (wldr) wv = __ldg(pwp);
    pkd++; pxp += sd; pwp += 9;
    if (pkd == kd_end) { pkd = kd0; pxp += xkd_wrap; pwp += wkd_wrap; }

    // store to buffer 0
    #pragma unroll
    for (int k=0; k<PASSES; k++)
        if (soff[k] >= 0) s_x[0][soff[k]] = rv[k];
    if (wldr) s_w[0][wslot] = pk2(wv, wv);
    __syncthreads();

    #pragma unroll 1
    for (int pp = 0; pp < P; pp++) {
        const int b = pp & 1;
        const bool more = (pp+1 < P);
        if (more) {
            #pragma unroll
            for (int k=0; k<PASSES; k++)
                rv[k] = (goff[k] >= 0) ? __ldg(pxp + goff[k]) : 0.f;
            if (wldr) wv = __ldg(pwp);
            pkd++; pxp += sd; pwp += 9;
            if (pkd == kd_end) { pkd = kd0; pxp += xkd_wrap; pwp += wkd_wrap; }
        }
        #pragma unroll
        for (int kh=0; kh<3; kh++) {
            const float2* x2 = (const float2*)&s_x[b][(ty+kh)*WPP + tx*PW];
            float2 A = x2[0], B = x2[1], C = x2[2], D = x2[3];
            u64 e0 = pk2(A.x, A.y), e1 = pk2(B.x, B.y);
            u64 e2 = pk2(C.x, C.y), e3 = pk2(D.x, D.y);
            u64 o0 = pk2(A.y, B.x), o1 = pk2(B.y, C.x), o2 = pk2(C.y, D.x);
            #pragma unroll
            for (int co=0; co<COT; co++) {
                ulonglong2 w01 = *(const ulonglong2*)&s_w[b][(co*3+kh)*4];
                u64 w2v = s_w[b][(co*3+kh)*4 + 2];
                acc2[co][0] = fma2(w01.x, e0, acc2[co][0]);
                acc2[co][1] = fma2(w01.x, e1, acc2[co][1]);
                acc2[co][2] = fma2(w01.x, e2, acc2[co][2]);
                acc2[co][0] = fma2(w01.y, o0, acc2[co][0]);
                acc2[co][1] = fma2(w01.y, o1, acc2[co][1]);
                acc2[co][2] = fma2(w01.y, o2, acc2[co][2]);
                acc2[co][0] = fma2(w2v, e1, acc2[co][0]);
                acc2[co][1] = fma2(w2v, e2, acc2[co][1]);
                acc2[co][2] = fma2(w2v, e3, acc2[co][2]);
            }
        }
        if (more) {
            const int b2 = (pp+1) & 1;
            #pragma unroll
            for (int k=0; k<PASSES; k++)
                if (soff[k] >= 0) s_x[b2][soff[k]] = rv[k];
            if (wldr) s_w[b2][wslot] = pk2(wv, wv);
        }
        __syncthreads();
    }

    // ---- epilogue: bias, store, fused per-channel stats ----
    const int h = h0 + ty;
    #pragma unroll
    for (int co=0; co<COT; co++) {
        float bv = __ldg(&bias[co0+co]);
        long base = (((long)(clip*BB+n)*COUT + co0+co)*CF + d)*((long)HS*WS) + h*WS + tx*PW;
        float cs = 0.f, cs2 = 0.f;
        #pragma unroll
        for (int j=0; j<PH; j++) {
            float lo, hi; upk2(acc2[co][j], lo, hi);
            lo += bv; hi += bv;
            y[base + 2*j]     = lo;
            y[base + 2*j + 1] = hi;
            cs += lo + hi;
            cs2 = fmaf(lo, lo, fmaf(hi, hi, cs2));
        }
        #pragma unroll
        for (int o=16; o>0; o>>=1) {
            cs  += __shfl_xor_sync(0xffffffff, cs,  o);
            cs2 += __shfl_xor_sync(0xffffffff, cs2, o);
        }
        if (lane == 0) { s_red[wid][co][0] = cs; s_red[wid][co][1] = cs2; }
    }
    __syncthreads();
    if (tid < COT) {
        double ds = 0.0, ds2 = 0.0;
        #pragma unroll
        for (int wi=0; wi<NW; wi++) { ds += (double)s_red[wi][tid][0]; ds2 += (double)s_red[wi][tid][1]; }
        double* st = g_stats + (long)stage*CLIPS*256 + clip*256;
        atomicAdd(&st[co0+tid], ds);
        atomicAdd(&st[128 + co0+tid], ds2);
    }
}

// ---------------- finalize stats (re-zeros accumulators) ----------------
__global__ void finalize_stats_k(const float* __restrict__ gma, const float* __restrict__ bet,
                                 int stage, int C, double cnt)
{
    int clip = blockIdx.x, c = threadIdx.x;
    if (c < C) {
        double* st = g_stats + (long)stage*CLIPS*256 + clip*256;
        double m = st[c] / cnt;
        double v = st[128 + c] / cnt - m*m;
        st[c] = 0.0; st[128 + c] = 0.0;
        double sc = (double)gma[c] / sqrt(v + 1e-5);
        g_scale[clip*128 + c] = (float)sc;
        g_shift[clip*128 + c] = (float)((double)bet[c] - m*sc);
    }
}

// ---------------- BN + ReLU + maxpool(1,2,2) ----------------
__global__ void bn_maxpool_k(const float* __restrict__ y, float* __restrict__ out,
                             int C, int H, int W)
{
    int HO = H/2, WO = W/2;
    long total = (long)CLIPS*BB*C*CF*HO*WO;
    for (long o = (long)blockIdx.x*blockDim.x + threadIdx.x; o < total; o += (long)gridDim.x*blockDim.x) {
        int wo = o % WO; long t = o / WO;
        int ho = t % HO; t /= HO;
        int d  = t % CF; t /= CF;
        int c  = t % C;  t /= C;
        int n  = t % BB; int clip = t / BB;
        float sc = g_scale[clip*128 + c], sh = g_shift[clip*128 + c];
        const float* p = y + (((long)((clip*BB+n)*C + c)*CF + d)*H + 2*ho)*W + 2*wo;
        float a0 = fmaxf(fmaf(sc, p[0],   sh), 0.f);
        float a1 = fmaxf(fmaf(sc, p[1],   sh), 0.f);
        float a2 = fmaxf(fmaf(sc, p[W],   sh), 0.f);
        float a3 = fmaxf(fmaf(sc, p[W+1], sh), 0.f);
        out[o] = fmaxf(fmaxf(a0,a1), fmaxf(a2,a3));
    }
}

// ---------------- BN + ReLU + avgpool 6x6 -> flattened h ----------------
__global__ void bn_avgpool_k(const float* __restrict__ y)
{
    int idx = blockIdx.x*blockDim.x + threadIdx.x;
    if (idx >= CLIPS*BB*128*16*16) return;
    int wo = idx & 3;
    int ho = (idx >> 2) & 3;
    int d  = (idx >> 4) & 15;
    int c  = (idx >> 8) & 127;
    int n  = (idx >> 15) & 3;
    int clip = idx >> 17;
    float sc = g_scale[clip*128 + c], sh = g_shift[clip*128 + c];
    const float* p = y + ((((long)(clip*BB+n)*128 + c)*CF + d)*24 + 6*ho)*24 + 6*wo;
    float s = 0.f;
    #pragma unroll
    for (int i=0;i<6;i++)
        #pragma unroll
        for (int j=0;j<6;j++)
            s += fmaxf(fmaf(sc, p[i*24+j], sh), 0.f);
    g_h[(long)(clip*BB+n)*32768 + c*256 + d*16 + ho*4 + wo] = s * (1.f/36.f);
}

// ---------------- batched projection ----------------
__global__ void proj_k(const float* __restrict__ pw, const float* __restrict__ pb)
{
    int co = blockIdx.x;
    int t = threadIdx.x;
    float part[28];
    #pragma unroll
    for (int r=0;r<28;r++) part[r] = 0.f;
    const float* wrow = pw + (long)co*32768;
    for (int j = t; j < 32768; j += 256) {
        float wv = wrow[j];
        #pragma unroll
        for (int r=0;r<28;r++)
            part[r] = fmaf(wv, g_h[(long)r*32768 + j], part[r]);
    }
    #pragma unroll
    for (int r=0;r<28;r++)
        #pragma unroll
        for (int o=16;o>0;o>>=1)
            part[r] += __shfl_xor_sync(0xffffffff, part[r], o);
    __shared__ float sred[28][8];
    int wa = t >> 5, l = t & 31;
    if (l == 0) {
        #pragma unroll
        for (int r=0;r<28;r++) sred[r][wa] = part[r];
    }
    __syncthreads();
    if (t < 28) {
        float a = 0.f;
        #pragma unroll
        for (int k=0;k<8;k++) a += sred[t][k];
        int clip = t >> 2, b_ = t & 3;
        g_feat[(b_*CLIPS + clip)*DC + co] = a + pb[co];
    }
}

// ---------------- VQ argmin ----------------
__global__ void quant_score_k(const float* __restrict__ cb)
{
    int row = blockIdx.x;
    int k = blockIdx.y*256 + threadIdx.x;
    __shared__ float sf[DC];
    sf[threadIdx.x] = g_feat[row*DC + threadIdx.x];
    __syncthreads();
    const float4* c4 = (const float4*)(cb + (long)k*DC);
    const float4* f4 = (const float4*)sf;
    float dot = 0.f, cn = 0.f;
    #pragma unroll 8
    for (int j=0; j<64; j++) {
        float4 c = c4[j]; float4 f = f4[j];
        dot = fmaf(c.x,f.x,dot); dot = fmaf(c.y,f.y,dot);
        dot = fmaf(c.z,f.z,dot); dot = fmaf(c.w,f.w,dot);
        cn  = fmaf(c.x,c.x,cn);  cn  = fmaf(c.y,c.y,cn);
        cn  = fmaf(c.z,c.z,cn);  cn  = fmaf(c.w,c.w,cn);
    }
    float score = cn - 2.f*dot;
    __shared__ float ss[256];
    __shared__ int   si[256];
    ss[threadIdx.x] = score; si[threadIdx.x] = k;
    __syncthreads();
    for (int o=128; o>0; o>>=1) {
        if (threadIdx.x < o) {
            float s2 = ss[threadIdx.x+o]; int i2 = si[threadIdx.x+o];
            if (s2 < ss[threadIdx.x] || (s2 == ss[threadIdx.x] && i2 < si[threadIdx.x])) {
                ss[threadIdx.x] = s2; si[threadIdx.x] = i2;
            }
        }
        __syncthreads();
    }
    if (threadIdx.x == 0) { g_part_s[row*32+blockIdx.y] = ss[0]; g_part_i[row*32+blockIdx.y] = si[0]; }
}

__global__ void quant_reduce_k(const float* __restrict__ cb)
{
    int row = blockIdx.x;
    __shared__ int bi;
    if (threadIdx.x == 0) {
        float s = g_part_s[row*32]; int i = g_part_i[row*32];
        for (int j=1; j<32; j++) {
            float s2 = g_part_s[row*32+j]; int i2 = g_part_i[row*32+j];
            if (s2 < s || (s2 == s && i2 < i)) { s = s2; i = i2; }
        }
        g_tok[row] = i; bi = i;
    }
    __syncthreads();
    const float* crow = cb + (long)bi*DC;
    for (int j = threadIdx.x; j < DC; j += blockDim.x)
        g_quant[row*DC+j] = crow[j];
}

// ---------------- GRU input gates (parallel over b,t) ----------------
__global__ void gru_gx_k(const float* __restrict__ wih, const float* __restrict__ bih)
{
    int bt = blockIdx.x;
    int g = blockIdx.y*128 + threadIdx.x;
    int b_ = bt/6, t = bt%6;
    __shared__ float sq[DC];
    sq[threadIdx.x]     = g_quant[(b_*CLIPS+t)*DC + threadIdx.x];
    sq[threadIdx.x+128] = g_quant[(b_*CLIPS+t)*DC + 128 + threadIdx.x];
    __syncthreads();
    const float4* w4 = (const float4*)(wih + (long)g*DC);
    const float4* q4 = (const float4*)sq;
    float a = bih[g];
    #pragma unroll 8
    for (int j=0;j<64;j++) {
        float4 w = w4[j], q = q4[j];
        a = fmaf(w.x,q.x,a); a = fmaf(w.y,q.y,a); a = fmaf(w.z,q.z,a); a = fmaf(w.w,q.w,a);
    }
    g_gx[bt*768 + g] = a;
}

// ---------------- fused GRU recurrence: 1 block per batch ----------------
__global__ void gru_fused_k(const float* __restrict__ whh, const float* __restrict__ bhh)
{
    int b_ = blockIdx.x, d = threadIdx.x;     // 256 threads
    __shared__ float s_h[DC];
    s_h[d] = 0.f;
    __syncthreads();
    const float4* wr4 = (const float4*)(whh + (long)d*DC);
    const float4* wz4 = (const float4*)(whh + (long)(256+d)*DC);
    const float4* wn4 = (const float4*)(whh + (long)(512+d)*DC);
    float br = bhh[d], bz = bhh[256+d], bn_ = bhh[512+d];
    for (int t=0; t<6; t++) {
        float hr = br, hz = bz, hn = bn_;
        const float4* h4 = (const float4*)s_h;
        #pragma unroll 8
        for (int j=0; j<64; j++) {
            float4 h = h4[j];
            float4 a = wr4[j], bzv = wz4[j], c = wn4[j];
            hr = fmaf(a.x,h.x,hr); hr = fmaf(a.y,h.y,hr); hr = fmaf(a.z,h.z,hr); hr = fmaf(a.w,h.w,hr);
            hz = fmaf(bzv.x,h.x,hz); hz = fmaf(bzv.y,h.y,hz); hz = fmaf(bzv.z,h.z,hz); hz = fmaf(bzv.w,h.w,hz);
            hn = fmaf(c.x,h.x,hn); hn = fmaf(c.y,h.y,hn); hn = fmaf(c.z,h.z,hn); hn = fmaf(c.w,h.w,hn);
        }
        int bt = b_*6 + t;
        float xr = g_gx[bt*768 + d];
        float xz = g_gx[bt*768 + 256 + d];
        float xn = g_gx[bt*768 + 512 + d];
        float r = 1.f/(1.f + expf(-(xr+hr)));
        float z = 1.f/(1.f + expf(-(xz+hz)));
        float nn = tanhf(xn + r*hn);
        float h2 = (1.f - z)*nn + z*s_h[d];
        __syncthreads();
        s_h[d] = h2;
        g_ctx[bt*DC + d] = h2;
        __syncthreads();
    }
}

// ---------------- fused losses + output assembly ----------------
__global__ void loss_final_k(float* __restrict__ out)
{
    int t = threadIdx.x;
    float s0 = 0.f, s1 = 0.f;
    for (int i = t; i < BB*CLIPS*DC; i += 256) {
        float dd = g_feat[i] - g_quant[i];
        s0 = fmaf(dd, dd, s0);
    }
    for (int i = t; i < BB*6*DC; i += 256) {
        int d = i % DC; int tt = (i/DC) % 6; int b_ = i/(6*DC);
        float diff = g_ctx[i] - g_feat[(b_*CLIPS + tt + 1)*DC + d];
        s1 = fmaf(diff, diff, s1);
    }
    __shared__ float sh0[256], sh1[256];
    sh0[t] = s0; sh1[t] = s1; __syncthreads();
    for (int o=128; o>0; o>>=1) {
        if (t < o) { sh0[t] += sh0[t+o]; sh1[t] += sh1[t+o]; }
        __syncthreads();
    }
    for (int i = t; i < BB*CLIPS; i += 256) out[i] = (float)g_tok[i];
    for (int i = t; i < BB*CLIPS*DC; i += 256) out[28 + i] = g_quant[i];
    if (t == 0) {
        float c = sh0[0] / (float)(BB*CLIPS*DC);
        float x = sh1[0] / (float)(BB*6*DC);
        out[28 + 7168 + 0] = c;
        out[28 + 7168 + 1] = c;
        out[28 + 7168 + 2] = x;
        out[28 + 7168 + 3] = c + 0.25f*c + 0.1f*x;
    }
}

// ---------------- host launcher ----------------
extern "C" void kernel_launch(void* const* d_in, const int* in_sizes, int n_in,
                              void* d_out, int out_size)
{
    const float* x   = (const float*)d_in[0];
    const float* c1w = (const float*)d_in[1];
    const float* c1b = (const float*)d_in[2];
    const float* g1  = (const float*)d_in[3];
    const float* b1  = (const float*)d_in[4];
    const float* c2w = (const float*)d_in[5];
    const float* c2b = (const float*)d_in[6];
    const float* g2  = (const float*)d_in[7];
    const float* b2  = (const float*)d_in[8];
    const float* c3w = (const float*)d_in[9];
    const float* c3b = (const float*)d_in[10];
    const float* g3  = (const float*)d_in[11];
    const float* b3  = (const float*)d_in[12];
    const float* pw  = (const float*)d_in[13];
    const float* pb  = (const float*)d_in[14];
    const float* cb  = (const float*)d_in[15];
    const float* wih = (const float*)d_in[16];
    const float* whh = (const float*)d_in[17];
    const float* bih = (const float*)d_in[18];
    const float* bhh = (const float*)d_in[19];
    float* out = (float*)d_out;

    float *y1, *p1, *y2, *p2, *y3;
    cudaGetSymbolAddress((void**)&y1, g_y1);
    cudaGetSymbolAddress((void**)&p1, g_p1);
    cudaGetSymbolAddress((void**)&y2, g_y2);
    cudaGetSymbolAddress((void**)&p2, g_p2);
    cudaGetSymbolAddress((void**)&y3, g_y3);

    // stage 1: conv1 (stats fused)
    conv3d_k<3,32,96,96,8,8,128><<<dim3(12,4,CLIPS*64), dim3(16,8)>>>(
        x, 0L, (long)3*64*96*96, (long)64*96*96, (long)96*96, 8, c1w, c1b, y1, 0);
    finalize_stats_k<<<CLIPS,128>>>(g1, b1, 0, 32, (double)(BB*16*96*96));
    bn_maxpool_k<<<129024,256>>>(y1, p1, 32, 96, 96);

    // stage 2: conv2 (stats fused)
    conv3d_k<32,64,48,48,16,8,128><<<dim3(3,8,CLIPS*64), dim3(8,16)>>>(
        p1, (long)BB*32*16*48*48, (long)32*16*48*48, (long)16*48*48, (long)48*48, 0, c2w, c2b, y2, 1);
    finalize_stats_k<<<CLIPS,128>>>(g2, b2, 1, 64, (double)(BB*16*48*48));
    bn_maxpool_k<<<64512,256>>>(y2, p2, 64, 48, 48);

    // stage 3: conv3 (stats fused)
    conv3d_k<64,128,24,24,24,8,96><<<dim3(1,16,CLIPS*64), dim3(4,24)>>>(
        p2, (long)BB*64*16*24*24, (long)64*16*24*24, (long)16*24*24, (long)24*24, 0, c3w, c3b, y3, 2);
    finalize_stats_k<<<CLIPS,128>>>(g3, b3, 2, 128, (double)(BB*16*24*24));
    bn_avgpool_k<<<3584,256>>>(y3);

    // projection + VQ + GRU + losses
    proj_k<<<256,256>>>(pw, pb);
    quant_score_k<<<dim3(28,32),256>>>(cb);
    quant_reduce_k<<<28,64>>>(cb);
    gru_gx_k<<<dim3(24,6),128>>>(wih, bih);
    gru_fused_k<<<4,256>>>(whh, bhh);
    loss_final_k<<<1,256>>>(out);
}

// round 7
// speedup vs baseline: 1.3409x; 1.3409x over previous
#include <cuda_runtime.h>
#include <math.h>

#define BB 4
#define CF 16
#define CLIPS 7
#define DC 256
#define KC 8192

typedef unsigned long long u64;
typedef unsigned int u32;

// ---------------- scratch ----------------
__device__ float g_y1[CLIPS*BB*32*CF*96*96];
__device__ float g_p1[CLIPS*BB*32*CF*48*48];
__device__ float g_y2[CLIPS*BB*64*CF*48*48];
__device__ float g_p2[CLIPS*BB*64*CF*24*24];
__device__ float g_y3[CLIPS*BB*128*CF*24*24];
__device__ float g_h [CLIPS*BB*32768];
__device__ float g_feat[BB*CLIPS*DC];
__device__ float g_quant[BB*CLIPS*DC];
__device__ int   g_tok[BB*CLIPS];
__device__ double g_stats[3*CLIPS*256];   // zero-init; finalize re-zeros (replay-safe)
__device__ float g_scale[CLIPS*128];
__device__ float g_shift[CLIPS*128];
__device__ float g_part_s[28*32];
__device__ int   g_part_i[28*32];
__device__ float g_gx[BB*6*768];
__device__ float g_ctx[BB*6*DC];

// ---------------- bf16 mma helpers (sm_80 PTX; legal on compute_103) ----------------
__device__ __forceinline__ u32 pkbf(float even_e, float odd_e) {
    // returns bf16x2 reg: low16 = bf16(even_e), high16 = bf16(odd_e)
    u32 r; asm("cvt.rn.bf16x2.f32 %0, %1, %2;" : "=r"(r) : "f"(odd_e), "f"(even_e));
    return r;
}
__device__ __forceinline__ void mma_bf(float (&d)[4],
                                       u32 a0, u32 a1, u32 a2, u32 a3,
                                       u32 b0, u32 b1) {
    asm volatile(
        "mma.sync.aligned.m16n8k16.row.col.f32.bf16.bf16.f32 "
        "{%0,%1,%2,%3},{%4,%5,%6,%7},{%8,%9},{%0,%1,%2,%3};"
        : "+f"(d[0]), "+f"(d[1]), "+f"(d[2]), "+f"(d[3])
        : "r"(a0), "r"(a1), "r"(a2), "r"(a3), "r"(b0), "r"(b1));
}

// ============ conv3d k=3 pad=1 as implicit GEMM on mma.sync bf16 (3-term split) ====
// grid: (M/128, COUT/NT, 28), block 256 (8 warps; warp w owns rows 16w..16w+15)
template<int CIN, int NT, int HS, int WS, int KREAL, int CHUNKS>
__global__ void __launch_bounds__(256)
convmma_k(const float* __restrict__ xin, long sn, long scl, long sc, long sd,
          const float* __restrict__ wgt, const float* __restrict__ bias,
          float* __restrict__ y, int coutall, int stage)
{
    constexpr int PL  = HS*WS;
    constexpr int PLC = CF*PL;
    constexpr int NT8 = NT/8;
    constexpr int TPR = 256/NT;     // threads per B row
    constexpr int KPT = 32/TPR;     // k elems per thread for B

    __shared__ u32  sA[2][128][20]; // [hi|lo][row][k-word], padded row (bank-safe)
    __shared__ u32  sB[2][64][20];
    __shared__ int4 s_tup[2][32];
    __shared__ float4 s_red[8][32];

    const int t = threadIdx.x;
    const int warp = t >> 5, lane = t & 31;
    const int z = blockIdx.z, clip = z >> 2, nb = z & 3;
    const int co0 = blockIdx.y * NT;

    // A-gather geometry (2 threads per row, 16 k each)
    const int ar  = t >> 1;
    const int ak0 = (t & 1) * 16;
    const int posA = blockIdx.x*128 + ar;
    const int d  = posA / PL;
    const int rr = posA - d*PL;
    const int h  = rr / WS;
    const int w_ = rr - h*WS;
    const float* pbase = xin + (long)nb*sn + (long)clip*scl + posA;

    // B-gather geometry
    const int bn  = t / TPR;
    const int bk0 = (t % TPR) * KPT;
    const float* wrow = wgt + (long)(co0 + bn)*KREAL;

    float acc[NT8][4];
    #pragma unroll
    for (int i=0;i<NT8;i++) { acc[i][0]=0.f; acc[i][1]=0.f; acc[i][2]=0.f; acc[i][3]=0.f; }

    // tuples for chunk 0
    if (t < 32) {
        int k = t; int4 tp;
        if (k < KREAL) {
            int ci = k/27; int r = k - ci*27;
            int kd = r/9;  int r2 = r - kd*9;
            int kh = r2/3; int kw = r2 - kh*3;
            tp.x = ci*(int)sc + (kd-1)*(int)sd + (kh-1)*WS + (kw-1);
            tp.y = kd-1; tp.z = kh-1; tp.w = kw-1;
        } else { tp.x = 0; tp.y = -1000; tp.z = 0; tp.w = 0; }
        s_tup[0][t] = tp;
    }
    __syncthreads();

    #pragma unroll 1
    for (int c = 0; c < CHUNKS; c++) {
        const int cb = c & 1;
        const int kbase = c*32;
        // ---- gather A (hi/lo bf16 split) ----
        #pragma unroll
        for (int jp = 0; jp < 8; jp++) {
            float v0, v1;
            {
                int4 tp = s_tup[cb][ak0 + 2*jp];
                int dd = d + tp.y, hh = h + tp.z, ww = w_ + tp.w;
                bool ok = ((u32)dd < (u32)CF) && ((u32)hh < (u32)HS) && ((u32)ww < (u32)WS);
                v0 = ok ? __ldg(pbase + tp.x) : 0.f;
            }
            {
                int4 tp = s_tup[cb][ak0 + 2*jp + 1];
                int dd = d + tp.y, hh = h + tp.z, ww = w_ + tp.w;
                bool ok = ((u32)dd < (u32)CF) && ((u32)hh < (u32)HS) && ((u32)ww < (u32)WS);
                v1 = ok ? __ldg(pbase + tp.x) : 0.f;
            }
            u32 hw = pkbf(v0, v1);
            float h0 = __uint_as_float(hw << 16);
            float h1 = __uint_as_float(hw & 0xffff0000u);
            u32 lw = pkbf(v0 - h0, v1 - h1);
            sA[0][ar][(ak0 >> 1) + jp] = hw;
            sA[1][ar][(ak0 >> 1) + jp] = lw;
        }
        // ---- gather B ----
        #pragma unroll
        for (int jp = 0; jp < KPT/2; jp++) {
            int k0 = kbase + bk0 + 2*jp;
            float v0 = (k0   < KREAL) ? __ldg(wrow + k0)   : 0.f;
            float v1 = (k0+1 < KREAL) ? __ldg(wrow + k0+1) : 0.f;
            u32 hw = pkbf(v0, v1);
            float h0 = __uint_as_float(hw << 16);
            float h1 = __uint_as_float(hw & 0xffff0000u);
            u32 lw = pkbf(v0 - h0, v1 - h1);
            sB[0][bn][(bk0 >> 1) + jp] = hw;
            sB[1][bn][(bk0 >> 1) + jp] = lw;
        }
        __syncthreads();

        // ---- prefetch tuples for next chunk (warp 0 lanes) ----
        if (t < 32 && c+1 < CHUNKS) {
            int k = (c+1)*32 + t; int4 tp;
            if (k < KREAL) {
                int ci = k/27; int r = k - ci*27;
                int kd = r/9;  int r2 = r - kd*9;
                int kh = r2/3; int kw = r2 - kh*3;
                tp.x = ci*(int)sc + (kd-1)*(int)sd + (kh-1)*WS + (kw-1);
                tp.y = kd-1; tp.z = kh-1; tp.w = kw-1;
            } else { tp.x = 0; tp.y = -1000; tp.z = 0; tp.w = 0; }
            s_tup[(c+1)&1][t] = tp;
        }

        // ---- mma ----
        const int ra = (warp << 4) + (lane >> 2);
        #pragma unroll
        for (int ks = 0; ks < 2; ks++) {
            const int kw0 = ks*8 + (lane & 3);
            u32 ah0 = sA[0][ra][kw0],     ah2 = sA[0][ra][kw0+4];
            u32 ah1 = sA[0][ra+8][kw0],   ah3 = sA[0][ra+8][kw0+4];
            u32 al0 = sA[1][ra][kw0],     al2 = sA[1][ra][kw0+4];
            u32 al1 = sA[1][ra+8][kw0],   al3 = sA[1][ra+8][kw0+4];
            #pragma unroll
            for (int nt = 0; nt < NT8; nt++) {
                const int rb = nt*8 + (lane >> 2);
                u32 bh0 = sB[0][rb][kw0], bh1 = sB[0][rb][kw0+4];
                u32 bl0 = sB[1][rb][kw0], bl1 = sB[1][rb][kw0+4];
                mma_bf(acc[nt], ah0, ah1, ah2, ah3, bh0, bh1);
                mma_bf(acc[nt], ah0, ah1, ah2, ah3, bl0, bl1);
                mma_bf(acc[nt], al0, al1, al2, al3, bh0, bh1);
            }
        }
        __syncthreads();
    }

    // ---- epilogue: bias, store, fused BN stats (deterministic) ----
    const int r0 = blockIdx.x*128 + (warp << 4) + (lane >> 2);
    float* yb = y + ((long)(clip*BB + nb)*coutall + co0)*(long)PLC;
    #pragma unroll
    for (int nt = 0; nt < NT8; nt++) {
        int c0 = nt*8 + 2*(lane & 3);
        float b0 = __ldg(&bias[co0 + c0]);
        float b1 = __ldg(&bias[co0 + c0 + 1]);
        float v00 = acc[nt][0] + b0;
        float v01 = acc[nt][1] + b1;
        float v10 = acc[nt][2] + b0;
        float v11 = acc[nt][3] + b1;
        yb[(long)c0*PLC + r0]         = v00;
        yb[(long)(c0+1)*PLC + r0]     = v01;
        yb[(long)c0*PLC + r0 + 8]     = v10;
        yb[(long)(c0+1)*PLC + r0 + 8] = v11;
        float se = v00 + v10, so = v01 + v11;
        float qe = v00*v00 + v10*v10, qo = v01*v01 + v11*v11;
        #pragma unroll
        for (int o = 4; o <= 16; o <<= 1) {
            se += __shfl_xor_sync(0xffffffff, se, o);
            so += __shfl_xor_sync(0xffffffff, so, o);
            qe += __shfl_xor_sync(0xffffffff, qe, o);
            qo += __shfl_xor_sync(0xffffffff, qo, o);
        }
        if (lane < 4) s_red[warp][nt*4 + lane] = make_float4(se, so, qe, qo);
    }
    __syncthreads();
    if (t < NT) {
        int nt = t >> 3, cp = (t & 7) >> 1, odd = t & 1;
        double ds = 0.0, dq = 0.0;
        #pragma unroll
        for (int w8 = 0; w8 < 8; w8++) {
            float4 f = s_red[w8][nt*4 + cp];
            ds += (double)(odd ? f.y : f.x);
            dq += (double)(odd ? f.w : f.z);
        }
        double* st = g_stats + (long)stage*CLIPS*256 + clip*256;
        atomicAdd(&st[co0 + t], ds);
        atomicAdd(&st[128 + co0 + t], dq);
    }
}

// ---------------- finalize stats (re-zeros accumulators) ----------------
__global__ void finalize_stats_k(const float* __restrict__ gma, const float* __restrict__ bet,
                                 int stage, int C, double cnt)
{
    int clip = blockIdx.x, c = threadIdx.x;
    if (c < C) {
        double* st = g_stats + (long)stage*CLIPS*256 + clip*256;
        double m = st[c] / cnt;
        double v = st[128 + c] / cnt - m*m;
        st[c] = 0.0; st[128 + c] = 0.0;
        double sc = (double)gma[c] / sqrt(v + 1e-5);
        g_scale[clip*128 + c] = (float)sc;
        g_shift[clip*128 + c] = (float)((double)bet[c] - m*sc);
    }
}

// ---------------- BN + ReLU + maxpool(1,2,2) ----------------
__global__ void bn_maxpool_k(const float* __restrict__ y, float* __restrict__ out,
                             int C, int H, int W)
{
    int HO = H/2, WO = W/2;
    long total = (long)CLIPS*BB*C*CF*HO*WO;
    for (long o = (long)blockIdx.x*blockDim.x + threadIdx.x; o < total; o += (long)gridDim.x*blockDim.x) {
        int wo = o % WO; long t = o / WO;
        int ho = t % HO; t /= HO;
        int d  = t % CF; t /= CF;
        int c  = t % C;  t /= C;
        int n  = t % BB; int clip = t / BB;
        float sc = g_scale[clip*128 + c], sh = g_shift[clip*128 + c];
        const float* p = y + (((long)((clip*BB+n)*C + c)*CF + d)*H + 2*ho)*W + 2*wo;
        float a0 = fmaxf(fmaf(sc, p[0],   sh), 0.f);
        float a1 = fmaxf(fmaf(sc, p[1],   sh), 0.f);
        float a2 = fmaxf(fmaf(sc, p[W],   sh), 0.f);
        float a3 = fmaxf(fmaf(sc, p[W+1], sh), 0.f);
        out[o] = fmaxf(fmaxf(a0,a1), fmaxf(a2,a3));
    }
}

// ---------------- BN + ReLU + avgpool 6x6 -> flattened h ----------------
__global__ void bn_avgpool_k(const float* __restrict__ y)
{
    int idx = blockIdx.x*blockDim.x + threadIdx.x;
    if (idx >= CLIPS*BB*128*16*16) return;
    int wo = idx & 3;
    int ho = (idx >> 2) & 3;
    int d  = (idx >> 4) & 15;
    int c  = (idx >> 8) & 127;
    int n  = (idx >> 15) & 3;
    int clip = idx >> 17;
    float sc = g_scale[clip*128 + c], sh = g_shift[clip*128 + c];
    const float* p = y + ((((long)(clip*BB+n)*128 + c)*CF + d)*24 + 6*ho)*24 + 6*wo;
    float s = 0.f;
    #pragma unroll
    for (int i=0;i<6;i++)
        #pragma unroll
        for (int j=0;j<6;j++)
            s += fmaxf(fmaf(sc, p[i*24+j], sh), 0.f);
    g_h[(long)(clip*BB+n)*32768 + c*256 + d*16 + ho*4 + wo] = s * (1.f/36.f);
}

// ---------------- batched projection ----------------
__global__ void proj_k(const float* __restrict__ pw, const float* __restrict__ pb)
{
    int co = blockIdx.x;
    int t = threadIdx.x;
    float part[28];
    #pragma unroll
    for (int r=0;r<28;r++) part[r] = 0.f;
    const float* wrow = pw + (long)co*32768;
    for (int j = t; j < 32768; j += 256) {
        float wv = wrow[j];
        #pragma unroll
        for (int r=0;r<28;r++)
            part[r] = fmaf(wv, g_h[(long)r*32768 + j], part[r]);
    }
    #pragma unroll
    for (int r=0;r<28;r++)
        #pragma unroll
        for (int o=16;o>0;o>>=1)
            part[r] += __shfl_xor_sync(0xffffffff, part[r], o);
    __shared__ float sred[28][8];
    int wa = t >> 5, l = t & 31;
    if (l == 0) {
        #pragma unroll
        for (int r=0;r<28;r++) sred[r][wa] = part[r];
    }
    __syncthreads();
    if (t < 28) {
        float a = 0.f;
        #pragma unroll
        for (int k=0;k<8;k++) a += sred[t][k];
        int clip = t >> 2, b_ = t & 3;
        g_feat[(b_*CLIPS + clip)*DC + co] = a + pb[co];
    }
}

// ---------------- VQ argmin ----------------
__global__ void quant_score_k(const float* __restrict__ cb)
{
    int row = blockIdx.x;
    int k = blockIdx.y*256 + threadIdx.x;
    __shared__ float sf[DC];
    sf[threadIdx.x] = g_feat[row*DC + threadIdx.x];
    __syncthreads();
    const float4* c4 = (const float4*)(cb + (long)k*DC);
    const float4* f4 = (const float4*)sf;
    float dot = 0.f, cn = 0.f;
    #pragma unroll 8
    for (int j=0; j<64; j++) {
        float4 c = c4[j]; float4 f = f4[j];
        dot = fmaf(c.x,f.x,dot); dot = fmaf(c.y,f.y,dot);
        dot = fmaf(c.z,f.z,dot); dot = fmaf(c.w,f.w,dot);
        cn  = fmaf(c.x,c.x,cn);  cn  = fmaf(c.y,c.y,cn);
        cn  = fmaf(c.z,c.z,cn);  cn  = fmaf(c.w,c.w,cn);
    }
    float score = cn - 2.f*dot;
    __shared__ float ss[256];
    __shared__ int   si[256];
    ss[threadIdx.x] = score; si[threadIdx.x] = k;
    __syncthreads();
    for (int o=128; o>0; o>>=1) {
        if (threadIdx.x < o) {
            float s2 = ss[threadIdx.x+o]; int i2 = si[threadIdx.x+o];
            if (s2 < ss[threadIdx.x] || (s2 == ss[threadIdx.x] && i2 < si[threadIdx.x])) {
                ss[threadIdx.x] = s2; si[threadIdx.x] = i2;
            }
        }
        __syncthreads();
    }
    if (threadIdx.x == 0) { g_part_s[row*32+blockIdx.y] = ss[0]; g_part_i[row*32+blockIdx.y] = si[0]; }
}

__global__ void quant_reduce_k(const float* __restrict__ cb)
{
    int row = blockIdx.x;
    __shared__ int bi;
    if (threadIdx.x == 0) {
        float s = g_part_s[row*32]; int i = g_part_i[row*32];
        for (int j=1; j<32; j++) {
            float s2 = g_part_s[row*32+j]; int i2 = g_part_i[row*32+j];
            if (s2 < s || (s2 == s && i2 < i)) { s = s2; i = i2; }
        }
        g_tok[row] = i; bi = i;
    }
    __syncthreads();
    const float* crow = cb + (long)bi*DC;
    for (int j = threadIdx.x; j < DC; j += blockDim.x)
        g_quant[row*DC+j] = crow[j];
}

// ---------------- GRU input gates ----------------
__global__ void gru_gx_k(const float* __restrict__ wih, const float* __restrict__ bih)
{
    int bt = blockIdx.x;
    int g = blockIdx.y*128 + threadIdx.x;
    int b_ = bt/6, t = bt%6;
    __shared__ float sq[DC];
    sq[threadIdx.x]     = g_quant[(b_*CLIPS+t)*DC + threadIdx.x];
    sq[threadIdx.x+128] = g_quant[(b_*CLIPS+t)*DC + 128 + threadIdx.x];
    __syncthreads();
    const float4* w4 = (const float4*)(wih + (long)g*DC);
    const float4* q4 = (const float4*)sq;
    float a = bih[g];
    #pragma unroll 8
    for (int j=0;j<64;j++) {
        float4 w = w4[j], q = q4[j];
        a = fmaf(w.x,q.x,a); a = fmaf(w.y,q.y,a); a = fmaf(w.z,q.z,a); a = fmaf(w.w,q.w,a);
    }
    g_gx[bt*768 + g] = a;
}

// ---------------- fused GRU recurrence ----------------
__global__ void gru_fused_k(const float* __restrict__ whh, const float* __restrict__ bhh)
{
    int b_ = blockIdx.x, d = threadIdx.x;
    __shared__ float s_h[DC];
    s_h[d] = 0.f;
    __syncthreads();
    const float4* wr4 = (const float4*)(whh + (long)d*DC);
    const float4* wz4 = (const float4*)(whh + (long)(256+d)*DC);
    const float4* wn4 = (const float4*)(whh + (long)(512+d)*DC);
    float br = bhh[d], bz = bhh[256+d], bn_ = bhh[512+d];
    for (int t=0; t<6; t++) {
        float hr = br, hz = bz, hn = bn_;
        const float4* h4 = (const float4*)s_h;
        #pragma unroll 8
        for (int j=0; j<64; j++) {
            float4 h = h4[j];
            float4 a = wr4[j], bzv = wz4[j], c = wn4[j];
            hr = fmaf(a.x,h.x,hr); hr = fmaf(a.y,h.y,hr); hr = fmaf(a.z,h.z,hr); hr = fmaf(a.w,h.w,hr);
            hz = fmaf(bzv.x,h.x,hz); hz = fmaf(bzv.y,h.y,hz); hz = fmaf(bzv.z,h.z,hz); hz = fmaf(bzv.w,h.w,hz);
            hn = fmaf(c.x,h.x,hn); hn = fmaf(c.y,h.y,hn); hn = fmaf(c.z,h.z,hn); hn = fmaf(c.w,h.w,hn);
        }
        int bt = b_*6 + t;
        float xr = g_gx[bt*768 + d];
        float xz = g_gx[bt*768 + 256 + d];
        float xn = g_gx[bt*768 + 512 + d];
        float r = 1.f/(1.f + expf(-(xr+hr)));
        float z = 1.f/(1.f + expf(-(xz+hz)));
        float nn = tanhf(xn + r*hn);
        float h2 = (1.f - z)*nn + z*s_h[d];
        __syncthreads();
        s_h[d] = h2;
        g_ctx[bt*DC + d] = h2;
        __syncthreads();
    }
}

// ---------------- fused losses + output assembly ----------------
__global__ void loss_final_k(float* __restrict__ out)
{
    int t = threadIdx.x;
    float s0 = 0.f, s1 = 0.f;
    for (int i = t; i < BB*CLIPS*DC; i += 256) {
        float dd = g_feat[i] - g_quant[i];
        s0 = fmaf(dd, dd, s0);
    }
    for (int i = t; i < BB*6*DC; i += 256) {
        int d = i % DC; int tt = (i/DC) % 6; int b_ = i/(6*DC);
        float diff = g_ctx[i] - g_feat[(b_*CLIPS + tt + 1)*DC + d];
        s1 = fmaf(diff, diff, s1);
    }
    __shared__ float sh0[256], sh1[256];
    sh0[t] = s0; sh1[t] = s1; __syncthreads();
    for (int o=128; o>0; o>>=1) {
        if (t < o) { sh0[t] += sh0[t+o]; sh1[t] += sh1[t+o]; }
        __syncthreads();
    }
    for (int i = t; i < BB*CLIPS; i += 256) out[i] = (float)g_tok[i];
    for (int i = t; i < BB*CLIPS*DC; i += 256) out[28 + i] = g_quant[i];
    if (t == 0) {
        float c = sh0[0] / (float)(BB*CLIPS*DC);
        float x = sh1[0] / (float)(BB*6*DC);
        out[28 + 7168 + 0] = c;
        out[28 + 7168 + 1] = c;
        out[28 + 7168 + 2] = x;
        out[28 + 7168 + 3] = c + 0.25f*c + 0.1f*x;
    }
}

// ---------------- host launcher ----------------
extern "C" void kernel_launch(void* const* d_in, const int* in_sizes, int n_in,
                              void* d_out, int out_size)
{
    const float* x   = (const float*)d_in[0];
    const float* c1w = (const float*)d_in[1];
    const float* c1b = (const float*)d_in[2];
    const float* g1  = (const float*)d_in[3];
    const float* b1  = (const float*)d_in[4];
    const float* c2w = (const float*)d_in[5];
    const float* c2b = (const float*)d_in[6];
    const float* g2  = (const float*)d_in[7];
    const float* b2  = (const float*)d_in[8];
    const float* c3w = (const float*)d_in[9];
    const float* c3b = (const float*)d_in[10];
    const float* g3  = (const float*)d_in[11];
    const float* b3  = (const float*)d_in[12];
    const float* pw  = (const float*)d_in[13];
    const float* pb  = (const float*)d_in[14];
    const float* cb  = (const float*)d_in[15];
    const float* wih = (const float*)d_in[16];
    const float* whh = (const float*)d_in[17];
    const float* bih = (const float*)d_in[18];
    const float* bhh = (const float*)d_in[19];
    float* out = (float*)d_out;

    float *y1, *p1, *y2, *p2, *y3;
    cudaGetSymbolAddress((void**)&y1, g_y1);
    cudaGetSymbolAddress((void**)&p1, g_p1);
    cudaGetSymbolAddress((void**)&y2, g_y2);
    cudaGetSymbolAddress((void**)&p2, g_p2);
    cudaGetSymbolAddress((void**)&y3, g_y3);

    // stage 1: conv1  [4,3,64,96,96] clips -> [28][32][16][96][96]
    convmma_k<3,32,96,96,81,3><<<dim3(1152,1,28), 256>>>(
        x, (long)3*64*96*96, (long)8*96*96, (long)64*96*96, (long)96*96,
        c1w, c1b, y1, 32, 0);
    finalize_stats_k<<<CLIPS,128>>>(g1, b1, 0, 32, (double)(BB*16*96*96));
    bn_maxpool_k<<<129024,256>>>(y1, p1, 32, 96, 96);

    // stage 2: conv2  [28][32][16][48][48] -> [28][64][16][48][48]
    convmma_k<32,64,48,48,864,27><<<dim3(288,1,28), 256>>>(
        p1, (long)32*16*48*48, (long)4*32*16*48*48, (long)16*48*48, (long)48*48,
        c2w, c2b, y2, 64, 1);
    finalize_stats_k<<<CLIPS,128>>>(g2, b2, 1, 64, (double)(BB*16*48*48));
    bn_maxpool_k<<<64512,256>>>(y2, p2, 64, 48, 48);

    // stage 3: conv3  [28][64][16][24][24] -> [28][128][16][24][24]
    convmma_k<64,64,24,24,1728,54><<<dim3(72,2,28), 256>>>(
        p2, (long)64*16*24*24, (long)4*64*16*24*24, (long)16*24*24, (long)24*24,
        c3w, c3b, y3, 128, 2);
    finalize_stats_k<<<CLIPS,128>>>(g3, b3, 2, 128, (double)(BB*16*24*24));
    bn_avgpool_k<<<3584,256>>>(y3);

    // projection + VQ + GRU + losses
    proj_k<<<256,256>>>(pw, pb);
    quant_score_k<<<dim3(28,32),256>>>(cb);
    quant_reduce_k<<<28,64>>>(cb);
    gru_gx_k<<<dim3(24,6),128>>>(wih, bih);
    gru_fused_k<<<4,256>>>(whh, bhh);
    loss_final_k<<<1,256>>>(out);
}

// round 8
// speedup vs baseline: 1.4427x; 1.0759x over previous
#include <cuda_runtime.h>
#include <math.h>

#define BB 4
#define CF 16
#define CLIPS 7
#define DC 256
#define KC 8192

typedef unsigned long long u64;
typedef unsigned int u32;

// ---------------- scratch ----------------
__device__ float g_y1[CLIPS*BB*32*CF*96*96];
__device__ float g_p1[CLIPS*BB*32*CF*48*48];
__device__ float g_y2[CLIPS*BB*64*CF*48*48];
__device__ float g_p2[CLIPS*BB*64*CF*24*24];
__device__ float g_y3[CLIPS*BB*128*CF*24*24];
__device__ float g_h [CLIPS*BB*32768];
__device__ float g_feat[BB*CLIPS*DC];
__device__ float g_quant[BB*CLIPS*DC];
__device__ int   g_tok[BB*CLIPS];
__device__ double g_stats[3*CLIPS*256];   // zero-init; finalize re-zeros (replay-safe)
__device__ float g_scale[CLIPS*128];
__device__ float g_shift[CLIPS*128];
__device__ float g_part_s[28*32];
__device__ int   g_part_i[28*32];
__device__ float g_gx[BB*6*768];
__device__ float g_ctx[BB*6*DC];

// ---------------- bf16 mma helpers (sm_80-era PTX; legal on compute_103) ----------------
__device__ __forceinline__ u32 pkbf(float even_e, float odd_e) {
    u32 r; asm("cvt.rn.bf16x2.f32 %0, %1, %2;" : "=r"(r) : "f"(odd_e), "f"(even_e));
    return r;
}
__device__ __forceinline__ void mma_bf(float (&d)[4],
                                       const u32 (&a)[4], u32 b0, u32 b1) {
    asm volatile(
        "mma.sync.aligned.m16n8k16.row.col.f32.bf16.bf16.f32 "
        "{%0,%1,%2,%3},{%4,%5,%6,%7},{%8,%9},{%0,%1,%2,%3};"
        : "+f"(d[0]), "+f"(d[1]), "+f"(d[2]), "+f"(d[3])
        : "r"(a[0]), "r"(a[1]), "r"(a[2]), "r"(a[3]), "r"(b0), "r"(b1));
}
__device__ __forceinline__ void ldsm4(u32 (&r)[4], u32 addr) {
    asm volatile("ldmatrix.sync.aligned.m8n8.x4.shared.b16 {%0,%1,%2,%3}, [%4];"
        : "=r"(r[0]), "=r"(r[1]), "=r"(r[2]), "=r"(r[3]) : "r"(addr));
}
__device__ __forceinline__ u32 smem_u32(const void* p) {
    u32 a; asm("{ .reg .u64 t; cvta.to.shared.u64 t, %1; cvt.u32.u64 %0, t; }" : "=r"(a) : "l"(p));
    return a;
}

// smem word layout: sA [2][256][20] at 0, sB [2][64][20] at word 10240
#define SAW(s,r,w) ((s)*5120 + (r)*20 + (w))
#define SBW(s,r,w) (10240 + (s)*1280 + (r)*20 + (w))

// ============ conv3d k=3 pad=1 as implicit GEMM, CTA tile 256xNT, ldmatrix ============
// grid: (M/256, COUT/NT, 28), block 256 (8 warps; warp w owns rows 32w..32w+31)
template<int CIN, int NT, int HS, int WS, int KREAL, int CHUNKS>
__global__ void __launch_bounds__(256,2)
convmma_k(const float* __restrict__ xin, long sn, long scl, long sc, long sd,
          const float* __restrict__ wgt, const float* __restrict__ bias,
          float* __restrict__ y, int coutall, int stage)
{
    constexpr int PL  = HS*WS;
    constexpr int PLC = CF*PL;
    constexpr int NT8 = NT/8;      // n fragments
    constexpr int NP  = NT8/2;     // ldsm pairs for B
    constexpr int TPR = 256/NT;    // threads per B row
    constexpr int KPT = 32/TPR;    // k elems per thread for B

    extern __shared__ u32 dsm[];
    __shared__ int4   s_tup[2][32];
    __shared__ float4 s_red[8][32];

    const int t = threadIdx.x;
    const int warp = t >> 5, lane = t & 31;
    const int z = blockIdx.z, clip = z >> 2, nb = z & 3;
    const int co0 = blockIdx.y * NT;

    // A-gather: one thread per row
    const int posA = blockIdx.x*256 + t;
    const int d  = posA / PL;
    const int rr = posA - d*PL;
    const int h  = rr / WS;
    const int w_ = rr - h*WS;
    const float* pbase = xin + (long)nb*sn + (long)clip*scl + posA;

    // B-gather geometry
    const int bn  = t / TPR;
    const int bk0 = (t % TPR) * KPT;
    const float* wrow = wgt + (long)(co0 + bn)*KREAL;

    // ldmatrix lane geometry
    const int i7 = lane & 7, j3 = lane >> 3;
    const int a_row = warp*32 + (j3 & 1)*8 + i7;   // + mi*16
    const int a_wsel = (j3 >> 1) * 4;              // + ks*8
    const int b_row = (j3 >> 1)*8 + i7;            // + p*16
    const int b_wsel = (j3 & 1) * 4;               // + ks*8
    const u32 smb = smem_u32(dsm);

    float acc[2][NT8][4];
    #pragma unroll
    for (int mi=0;mi<2;mi++)
        #pragma unroll
        for (int i=0;i<NT8;i++) { acc[mi][i][0]=0.f; acc[mi][i][1]=0.f; acc[mi][i][2]=0.f; acc[mi][i][3]=0.f; }

    // tuples for chunk 0
    if (t < 32) {
        int k = t; int4 tp;
        if (k < KREAL) {
            int ci = k/27; int r = k - ci*27;
            int kd = r/9;  int r2 = r - kd*9;
            int kh = r2/3; int kw = r2 - kh*3;
            tp.x = ci*(int)sc + (kd-1)*(int)sd + (kh-1)*WS + (kw-1);
            tp.y = kd-1; tp.z = kh-1; tp.w = kw-1;
        } else { tp.x = 0; tp.y = -1000; tp.z = 0; tp.w = 0; }
        s_tup[0][t] = tp;
    }
    __syncthreads();

    #pragma unroll 1
    for (int c = 0; c < CHUNKS; c++) {
        const int cb = c & 1;
        const int kbase = c*32;
        // ---- gather A: this thread's row, all 32 k (hi/lo bf16 split) ----
        #pragma unroll
        for (int kk = 0; kk < 32; kk += 2) {
            float v0, v1;
            {
                int4 tp = s_tup[cb][kk];
                int dd = d + tp.y, hh = h + tp.z, ww = w_ + tp.w;
                bool ok = ((u32)dd < (u32)CF) && ((u32)hh < (u32)HS) && ((u32)ww < (u32)WS);
                v0 = ok ? __ldg(pbase + tp.x) : 0.f;
            }
            {
                int4 tp = s_tup[cb][kk+1];
                int dd = d + tp.y, hh = h + tp.z, ww = w_ + tp.w;
                bool ok = ((u32)dd < (u32)CF) && ((u32)hh < (u32)HS) && ((u32)ww < (u32)WS);
                v1 = ok ? __ldg(pbase + tp.x) : 0.f;
            }
            u32 hw = pkbf(v0, v1);
            float h0 = __uint_as_float(hw << 16);
            float h1 = __uint_as_float(hw & 0xffff0000u);
            u32 lw = pkbf(v0 - h0, v1 - h1);
            dsm[SAW(0, t, kk>>1)] = hw;
            dsm[SAW(1, t, kk>>1)] = lw;
        }
        // ---- gather B ----
        #pragma unroll
        for (int jp = 0; jp < KPT/2; jp++) {
            int k0 = kbase + bk0 + 2*jp;
            float v0 = (k0   < KREAL) ? __ldg(wrow + k0)   : 0.f;
            float v1 = (k0+1 < KREAL) ? __ldg(wrow + k0+1) : 0.f;
            u32 hw = pkbf(v0, v1);
            float h0 = __uint_as_float(hw << 16);
            float h1 = __uint_as_float(hw & 0xffff0000u);
            u32 lw = pkbf(v0 - h0, v1 - h1);
            dsm[SBW(0, bn, (bk0>>1)+jp)] = hw;
            dsm[SBW(1, bn, (bk0>>1)+jp)] = lw;
        }
        __syncthreads();

        // ---- prefetch tuples for next chunk ----
        if (t < 32 && c+1 < CHUNKS) {
            int k = (c+1)*32 + t; int4 tp;
            if (k < KREAL) {
                int ci = k/27; int r = k - ci*27;
                int kd = r/9;  int r2 = r - kd*9;
                int kh = r2/3; int kw = r2 - kh*3;
                tp.x = ci*(int)sc + (kd-1)*(int)sd + (kh-1)*WS + (kw-1);
                tp.y = kd-1; tp.z = kh-1; tp.w = kw-1;
            } else { tp.x = 0; tp.y = -1000; tp.z = 0; tp.w = 0; }
            s_tup[(c+1)&1][t] = tp;
        }

        // ---- mma via ldmatrix fragments ----
        #pragma unroll
        for (int ks = 0; ks < 2; ks++) {
            u32 ah[2][4], al[2][4];
            #pragma unroll
            for (int mi = 0; mi < 2; mi++) {
                ldsm4(ah[mi], smb + 4u*SAW(0, a_row + mi*16, ks*8 + a_wsel));
                ldsm4(al[mi], smb + 4u*SAW(1, a_row + mi*16, ks*8 + a_wsel));
            }
            #pragma unroll
            for (int p = 0; p < NP; p++) {
                u32 bh[4], bl[4];
                ldsm4(bh, smb + 4u*SBW(0, p*16 + b_row, ks*8 + b_wsel));
                ldsm4(bl, smb + 4u*SBW(1, p*16 + b_row, ks*8 + b_wsel));
                #pragma unroll
                for (int mi = 0; mi < 2; mi++) {
                    mma_bf(acc[mi][2*p],   ah[mi], bh[0], bh[1]);
                    mma_bf(acc[mi][2*p],   ah[mi], bl[0], bl[1]);
                    mma_bf(acc[mi][2*p],   al[mi], bh[0], bh[1]);
                    mma_bf(acc[mi][2*p+1], ah[mi], bh[2], bh[3]);
                    mma_bf(acc[mi][2*p+1], ah[mi], bl[2], bl[3]);
                    mma_bf(acc[mi][2*p+1], al[mi], bh[2], bh[3]);
                }
            }
        }
        __syncthreads();
    }

    // ---- epilogue: bias, store, fused BN stats (deterministic) ----
    const int r_base = blockIdx.x*256 + warp*32 + (lane >> 2);
    float* yb = y + ((long)(clip*BB + nb)*coutall + co0)*(long)PLC;
    #pragma unroll
    for (int nt = 0; nt < NT8; nt++) {
        int c0 = nt*8 + 2*(lane & 3);
        float b0 = __ldg(&bias[co0 + c0]);
        float b1 = __ldg(&bias[co0 + c0 + 1]);
        float se = 0.f, so = 0.f, qe = 0.f, qo = 0.f;
        #pragma unroll
        for (int mi = 0; mi < 2; mi++) {
            float v00 = acc[mi][nt][0] + b0;
            float v01 = acc[mi][nt][1] + b1;
            float v10 = acc[mi][nt][2] + b0;
            float v11 = acc[mi][nt][3] + b1;
            int r0 = r_base + mi*16;
            yb[(long)c0*PLC + r0]         = v00;
            yb[(long)(c0+1)*PLC + r0]     = v01;
            yb[(long)c0*PLC + r0 + 8]     = v10;
            yb[(long)(c0+1)*PLC + r0 + 8] = v11;
            se += v00 + v10;  so += v01 + v11;
            qe += v00*v00 + v10*v10;  qo += v01*v01 + v11*v11;
        }
        #pragma unroll
        for (int o = 4; o <= 16; o <<= 1) {
            se += __shfl_xor_sync(0xffffffff, se, o);
            so += __shfl_xor_sync(0xffffffff, so, o);
            qe += __shfl_xor_sync(0xffffffff, qe, o);
            qo += __shfl_xor_sync(0xffffffff, qo, o);
        }
        if (lane < 4) s_red[warp][nt*4 + lane] = make_float4(se, so, qe, qo);
    }
    __syncthreads();
    if (t < NT) {
        int nt = t >> 3, cp = (t & 7) >> 1, odd = t & 1;
        double ds = 0.0, dq = 0.0;
        #pragma unroll
        for (int w8 = 0; w8 < 8; w8++) {
            float4 f = s_red[w8][nt*4 + cp];
            ds += (double)(odd ? f.y : f.x);
            dq += (double)(odd ? f.w : f.z);
        }
        double* st = g_stats + (long)stage*CLIPS*256 + clip*256;
        atomicAdd(&st[co0 + t], ds);
        atomicAdd(&st[128 + co0 + t], dq);
    }
}

// ---------------- finalize stats (re-zeros accumulators) ----------------
__global__ void finalize_stats_k(const float* __restrict__ gma, const float* __restrict__ bet,
                                 int stage, int C, double cnt)
{
    int clip = blockIdx.x, c = threadIdx.x;
    if (c < C) {
        double* st = g_stats + (long)stage*CLIPS*256 + clip*256;
        double m = st[c] / cnt;
        double v = st[128 + c] / cnt - m*m;
        st[c] = 0.0; st[128 + c] = 0.0;
        double sc = (double)gma[c] / sqrt(v + 1e-5);
        g_scale[clip*128 + c] = (float)sc;
        g_shift[clip*128 + c] = (float)((double)bet[c] - m*sc);
    }
}

// ---------------- BN + ReLU + maxpool(1,2,2) ----------------
__global__ void bn_maxpool_k(const float* __restrict__ y, float* __restrict__ out,
                             int C, int H, int W)
{
    int HO = H/2, WO = W/2;
    long total = (long)CLIPS*BB*C*CF*HO*WO;
    for (long o = (long)blockIdx.x*blockDim.x + threadIdx.x; o < total; o += (long)gridDim.x*blockDim.x) {
        int wo = o % WO; long t = o / WO;
        int ho = t % HO; t /= HO;
        int d  = t % CF; t /= CF;
        int c  = t % C;  t /= C;
        int n  = t % BB; int clip = t / BB;
        float sc = g_scale[clip*128 + c], sh = g_shift[clip*128 + c];
        const float* p = y + (((long)((clip*BB+n)*C + c)*CF + d)*H + 2*ho)*W + 2*wo;
        float a0 = fmaxf(fmaf(sc, p[0],   sh), 0.f);
        float a1 = fmaxf(fmaf(sc, p[1],   sh), 0.f);
        float a2 = fmaxf(fmaf(sc, p[W],   sh), 0.f);
        float a3 = fmaxf(fmaf(sc, p[W+1], sh), 0.f);
        out[o] = fmaxf(fmaxf(a0,a1), fmaxf(a2,a3));
    }
}

// ---------------- BN + ReLU + avgpool 6x6 -> flattened h ----------------
__global__ void bn_avgpool_k(const float* __restrict__ y)
{
    int idx = blockIdx.x*blockDim.x + threadIdx.x;
    if (idx >= CLIPS*BB*128*16*16) return;
    int wo = idx & 3;
    int ho = (idx >> 2) & 3;
    int d  = (idx >> 4) & 15;
    int c  = (idx >> 8) & 127;
    int n  = (idx >> 15) & 3;
    int clip = idx >> 17;
    float sc = g_scale[clip*128 + c], sh = g_shift[clip*128 + c];
    const float* p = y + ((((long)(clip*BB+n)*128 + c)*CF + d)*24 + 6*ho)*24 + 6*wo;
    float s = 0.f;
    #pragma unroll
    for (int i=0;i<6;i++)
        #pragma unroll
        for (int j=0;j<6;j++)
            s += fmaxf(fmaf(sc, p[i*24+j], sh), 0.f);
    g_h[(long)(clip*BB+n)*32768 + c*256 + d*16 + ho*4 + wo] = s * (1.f/36.f);
}

// ---------------- batched projection ----------------
__global__ void proj_k(const float* __restrict__ pw, const float* __restrict__ pb)
{
    int co = blockIdx.x;
    int t = threadIdx.x;
    float part[28];
    #pragma unroll
    for (int r=0;r<28;r++) part[r] = 0.f;
    const float* wrow = pw + (long)co*32768;
    for (int j = t; j < 32768; j += 256) {
        float wv = wrow[j];
        #pragma unroll
        for (int r=0;r<28;r++)
            part[r] = fmaf(wv, g_h[(long)r*32768 + j], part[r]);
    }
    #pragma unroll
    for (int r=0;r<28;r++)
        #pragma unroll
        for (int o=16;o>0;o>>=1)
            part[r] += __shfl_xor_sync(0xffffffff, part[r], o);
    __shared__ float sred[28][8];
    int wa = t >> 5, l = t & 31;
    if (l == 0) {
        #pragma unroll
        for (int r=0;r<28;r++) sred[r][wa] = part[r];
    }
    __syncthreads();
    if (t < 28) {
        float a = 0.f;
        #pragma unroll
        for (int k=0;k<8;k++) a += sred[t][k];
        int clip = t >> 2, b_ = t & 3;
        g_feat[(b_*CLIPS + clip)*DC + co] = a + pb[co];
    }
}

// ---------------- VQ argmin ----------------
__global__ void quant_score_k(const float* __restrict__ cb)
{
    int row = blockIdx.x;
    int k = blockIdx.y*256 + threadIdx.x;
    __shared__ float sf[DC];
    sf[threadIdx.x] = g_feat[row*DC + threadIdx.x];
    __syncthreads();
    const float4* c4 = (const float4*)(cb + (long)k*DC);
    const float4* f4 = (const float4*)sf;
    float dot = 0.f, cn = 0.f;
    #pragma unroll 8
    for (int j=0; j<64; j++) {
        float4 c = c4[j]; float4 f = f4[j];
        dot = fmaf(c.x,f.x,dot); dot = fmaf(c.y,f.y,dot);
        dot = fmaf(c.z,f.z,dot); dot = fmaf(c.w,f.w,dot);
        cn  = fmaf(c.x,c.x,cn);  cn  = fmaf(c.y,c.y,cn);
        cn  = fmaf(c.z,c.z,cn);  cn  = fmaf(c.w,c.w,cn);
    }
    float score = cn - 2.f*dot;
    __shared__ float ss[256];
    __shared__ int   si[256];
    ss[threadIdx.x] = score; si[threadIdx.x] = k;
    __syncthreads();
    for (int o=128; o>0; o>>=1) {
        if (threadIdx.x < o) {
            float s2 = ss[threadIdx.x+o]; int i2 = si[threadIdx.x+o];
            if (s2 < ss[threadIdx.x] || (s2 == ss[threadIdx.x] && i2 < si[threadIdx.x])) {
                ss[threadIdx.x] = s2; si[threadIdx.x] = i2;
            }
        }
        __syncthreads();
    }
    if (threadIdx.x == 0) { g_part_s[row*32+blockIdx.y] = ss[0]; g_part_i[row*32+blockIdx.y] = si[0]; }
}

__global__ void quant_reduce_k(const float* __restrict__ cb)
{
    int row = blockIdx.x;
    __shared__ int bi;
    if (threadIdx.x == 0) {
        float s = g_part_s[row*32]; int i = g_part_i[row*32];
        for (int j=1; j<32; j++) {
            float s2 = g_part_s[row*32+j]; int i2 = g_part_i[row*32+j];
            if (s2 < s || (s2 == s && i2 < i)) { s = s2; i = i2; }
        }
        g_tok[row] = i; bi = i;
    }
    __syncthreads();
    const float* crow = cb + (long)bi*DC;
    for (int j = threadIdx.x; j < DC; j += blockDim.x)
        g_quant[row*DC+j] = crow[j];
}

// ---------------- GRU input gates ----------------
__global__ void gru_gx_k(const float* __restrict__ wih, const float* __restrict__ bih)
{
    int bt = blockIdx.x;
    int g = blockIdx.y*128 + threadIdx.x;
    int b_ = bt/6, t = bt%6;
    __shared__ float sq[DC];
    sq[threadIdx.x]     = g_quant[(b_*CLIPS+t)*DC + threadIdx.x];
    sq[threadIdx.x+128] = g_quant[(b_*CLIPS+t)*DC + 128 + threadIdx.x];
    __syncthreads();
    const float4* w4 = (const float4*)(wih + (long)g*DC);
    const float4* q4 = (const float4*)sq;
    float a = bih[g];
    #pragma unroll 8
    for (int j=0;j<64;j++) {
        float4 w = w4[j], q = q4[j];
        a = fmaf(w.x,q.x,a); a = fmaf(w.y,q.y,a); a = fmaf(w.z,q.z,a); a = fmaf(w.w,q.w,a);
    }
    g_gx[bt*768 + g] = a;
}

// ---------------- fused GRU recurrence ----------------
__global__ void gru_fused_k(const float* __restrict__ whh, const float* __restrict__ bhh)
{
    int b_ = blockIdx.x, d = threadIdx.x;
    __shared__ float s_h[DC];
    s_h[d] = 0.f;
    __syncthreads();
    const float4* wr4 = (const float4*)(whh + (long)d*DC);
    const float4* wz4 = (const float4*)(whh + (long)(256+d)*DC);
    const float4* wn4 = (const float4*)(whh + (long)(512+d)*DC);
    float br = bhh[d], bz = bhh[256+d], bn_ = bhh[512+d];
    for (int t=0; t<6; t++) {
        float hr = br, hz = bz, hn = bn_;
        const float4* h4 = (const float4*)s_h;
        #pragma unroll 8
        for (int j=0; j<64; j++) {
            float4 h = h4[j];
            float4 a = wr4[j], bzv = wz4[j], c = wn4[j];
            hr = fmaf(a.x,h.x,hr); hr = fmaf(a.y,h.y,hr); hr = fmaf(a.z,h.z,hr); hr = fmaf(a.w,h.w,hr);
            hz = fmaf(bzv.x,h.x,hz); hz = fmaf(bzv.y,h.y,hz); hz = fmaf(bzv.z,h.z,hz); hz = fmaf(bzv.w,h.w,hz);
            hn = fmaf(c.x,h.x,hn); hn = fmaf(c.y,h.y,hn); hn = fmaf(c.z,h.z,hn); hn = fmaf(c.w,h.w,hn);
        }
        int bt = b_*6 + t;
        float xr = g_gx[bt*768 + d];
        float xz = g_gx[bt*768 + 256 + d];
        float xn = g_gx[bt*768 + 512 + d];
        float r = 1.f/(1.f + expf(-(xr+hr)));
        float z = 1.f/(1.f + expf(-(xz+hz)));
        float nn = tanhf(xn + r*hn);
        float h2 = (1.f - z)*nn + z*s_h[d];
        __syncthreads();
        s_h[d] = h2;
        g_ctx[bt*DC + d] = h2;
        __syncthreads();
    }
}

// ---------------- fused losses + output assembly ----------------
__global__ void loss_final_k(float* __restrict__ out)
{
    int t = threadIdx.x;
    float s0 = 0.f, s1 = 0.f;
    for (int i = t; i < BB*CLIPS*DC; i += 256) {
        float dd = g_feat[i] - g_quant[i];
        s0 = fmaf(dd, dd, s0);
    }
    for (int i = t; i < BB*6*DC; i += 256) {
        int d = i % DC; int tt = (i/DC) % 6; int b_ = i/(6*DC);
        float diff = g_ctx[i] - g_feat[(b_*CLIPS + tt + 1)*DC + d];
        s1 = fmaf(diff, diff, s1);
    }
    __shared__ float sh0[256], sh1[256];
    sh0[t] = s0; sh1[t] = s1; __syncthreads();
    for (int o=128; o>0; o>>=1) {
        if (t < o) { sh0[t] += sh0[t+o]; sh1[t] += sh1[t+o]; }
        __syncthreads();
    }
    for (int i = t; i < BB*CLIPS; i += 256) out[i] = (float)g_tok[i];
    for (int i = t; i < BB*CLIPS*DC; i += 256) out[28 + i] = g_quant[i];
    if (t == 0) {
        float c = sh0[0] / (float)(BB*CLIPS*DC);
        float x = sh1[0] / (float)(BB*6*DC);
        out[28 + 7168 + 0] = c;
        out[28 + 7168 + 1] = c;
        out[28 + 7168 + 2] = x;
        out[28 + 7168 + 3] = c + 0.25f*c + 0.1f*x;
    }
}

// ---------------- host launcher ----------------
#define CONV_SMEM 51200

extern "C" void kernel_launch(void* const* d_in, const int* in_sizes, int n_in,
                              void* d_out, int out_size)
{
    const float* x   = (const float*)d_in[0];
    const float* c1w = (const float*)d_in[1];
    const float* c1b = (const float*)d_in[2];
    const float* g1  = (const float*)d_in[3];
    const float* b1  = (const float*)d_in[4];
    const float* c2w = (const float*)d_in[5];
    const float* c2b = (const float*)d_in[6];
    const float* g2  = (const float*)d_in[7];
    const float* b2  = (const float*)d_in[8];
    const float* c3w = (const float*)d_in[9];
    const float* c3b = (const float*)d_in[10];
    const float* g3  = (const float*)d_in[11];
    const float* b3  = (const float*)d_in[12];
    const float* pw  = (const float*)d_in[13];
    const float* pb  = (const float*)d_in[14];
    const float* cb  = (const float*)d_in[15];
    const float* wih = (const float*)d_in[16];
    const float* whh = (const float*)d_in[17];
    const float* bih = (const float*)d_in[18];
    const float* bhh = (const float*)d_in[19];
    float* out = (float*)d_out;

    float *y1, *p1, *y2, *p2, *y3;
    cudaGetSymbolAddress((void**)&y1, g_y1);
    cudaGetSymbolAddress((void**)&p1, g_p1);
    cudaGetSymbolAddress((void**)&y2, g_y2);
    cudaGetSymbolAddress((void**)&p2, g_p2);
    cudaGetSymbolAddress((void**)&y3, g_y3);

    cudaFuncSetAttribute(convmma_k<3,32,96,96,81,3>,
                         cudaFuncAttributeMaxDynamicSharedMemorySize, CONV_SMEM);
    cudaFuncSetAttribute(convmma_k<32,64,48,48,864,27>,
                         cudaFuncAttributeMaxDynamicSharedMemorySize, CONV_SMEM);
    cudaFuncSetAttribute(convmma_k<64,64,24,24,1728,54>,
                         cudaFuncAttributeMaxDynamicSharedMemorySize, CONV_SMEM);

    // stage 1: conv1  [4,3,64,96,96] clips -> [28][32][16][96][96]
    convmma_k<3,32,96,96,81,3><<<dim3(576,1,28), 256, CONV_SMEM>>>(
        x, (long)3*64*96*96, (long)8*96*96, (long)64*96*96, (long)96*96,
        c1w, c1b, y1, 32, 0);
    finalize_stats_k<<<CLIPS,128>>>(g1, b1, 0, 32, (double)(BB*16*96*96));
    bn_maxpool_k<<<129024,256>>>(y1, p1, 32, 96, 96);

    // stage 2: conv2  [28][32][16][48][48] -> [28][64][16][48][48]
    convmma_k<32,64,48,48,864,27><<<dim3(144,1,28), 256, CONV_SMEM>>>(
        p1, (long)32*16*48*48, (long)4*32*16*48*48, (long)16*48*48, (long)48*48,
        c2w, c2b, y2, 64, 1);
    finalize_stats_k<<<CLIPS,128>>>(g2, b2, 1, 64, (double)(BB*16*48*48));
    bn_maxpool_k<<<64512,256>>>(y2, p2, 64, 48, 48);

    // stage 3: conv3  [28][64][16][24][24] -> [28][128][16][24][24]
    convmma_k<64,64,24,24,1728,54><<<dim3(36,2,28), 256, CONV_SMEM>>>(
        p2, (long)64*16*24*24, (long)4*64*16*24*24, (long)16*24*24, (long)24*24,
        c3w, c3b, y3, 128, 2);
    finalize_stats_k<<<CLIPS,128>>>(g3, b3, 2, 128, (double)(BB*16*24*24));
    bn_avgpool_k<<<3584,256>>>(y3);

    // projection + VQ + GRU + losses
    proj_k<<<256,256>>>(pw, pb);
    quant_score_k<<<dim3(28,32),256>>>(cb);
    quant_reduce_k<<<28,64>>>(cb);
    gru_gx_k<<<dim3(24,6),128>>>(wih, bih);
    gru_fused_k<<<4,256>>>(whh, bhh);
    loss_final_k<<<1,256>>>(out);
}